// round 13
// baseline (speedup 1.0000x reference)
#include <cuda_runtime.h>
#include <stdint.h>

#define B_   2
#define N_   4096
#define E_   256
#define H_   8
#define HS_  32
#define BHTOT (B_*H_)
#define NW_  (N_/32)          // adj bitmask words per row

// Scratch:
//  g_Q : fp32 [B,H,N,HS]
//  g_K : tf32-rounded, FRAGMENT ORDER per (bh, 64-row tile)
//  g_V : tf32-rounded, fragment order with PV row permutation baked in
__device__ float    g_Q[(size_t)BHTOT * N_ * HS_];
__device__ float    g_K[(size_t)BHTOT * N_ * HS_];
__device__ float    g_V[(size_t)BHTOT * N_ * HS_];
__device__ unsigned g_adjbits[(size_t)B_ * N_ * NW_];
__device__ int      g_adj_mode;   // 0=int32{0,1}, 1=float32{0,1.0f}, 2=uint8{0,1}

// ---------------------------------------------------------------------------
// helpers
// ---------------------------------------------------------------------------
__device__ __forceinline__ uint32_t f2tf32(float f) {
    uint32_t r;
    asm("cvt.rna.tf32.f32 %0, %1;" : "=r"(r) : "f"(f));
    return r;
}
__device__ __forceinline__ float ex2(float x) {
    float r;
    asm("ex2.approx.f32 %0, %1;" : "=f"(r) : "f"(x));
    return r;
}
__device__ __forceinline__ void mma_tf32(float c[4], const uint32_t a[4],
                                         uint32_t b0, uint32_t b1) {
    asm volatile(
        "mma.sync.aligned.m16n8k8.row.col.f32.tf32.tf32.f32 "
        "{%0,%1,%2,%3}, {%4,%5,%6,%7}, {%8,%9}, {%0,%1,%2,%3};\n"
        : "+f"(c[0]), "+f"(c[1]), "+f"(c[2]), "+f"(c[3])
        : "r"(a[0]), "r"(a[1]), "r"(a[2]), "r"(a[3]), "r"(b0), "r"(b1));
}
#define CP_ASYNC16(dst_u32, src_ptr) \
    asm volatile("cp.async.ca.shared.global [%0], [%1], 16;\n" \
                 :: "r"(dst_u32), "l"(src_ptr))
#define CP_COMMIT() asm volatile("cp.async.commit_group;\n")
#define CP_WAIT(n)  asm volatile("cp.async.wait_group %0;\n" :: "n"(n))

// ---------------------------------------------------------------------------
// Detect adjacency storage dtype from bit patterns (deterministic, 64 KB scan).
// ---------------------------------------------------------------------------
__global__ __launch_bounds__(256) void detect_adj_kernel(const unsigned* __restrict__ a)
{
    __shared__ int s_ok[2];
    if (threadIdx.x == 0) { s_ok[0] = 1; s_ok[1] = 1; }
    __syncthreads();
    int ok_i = 1, ok_f = 1;
    for (int i = threadIdx.x; i < (1 << 14); i += 256) {
        unsigned w = a[i];
        if (w != 0u && w != 1u)          ok_i = 0;
        if (w != 0u && w != 0x3F800000u) ok_f = 0;
    }
    if (!ok_i) atomicAnd(&s_ok[0], 0);
    if (!ok_f) atomicAnd(&s_ok[1], 0);
    __syncthreads();
    if (threadIdx.x == 0) g_adj_mode = s_ok[0] ? 0 : (s_ok[1] ? 1 : 2);
}

// ---------------------------------------------------------------------------
// Pack adjacency to bitmask: g_adjbits[b*N + n][w] bit j = adj[b][n][w*32+j]
// ---------------------------------------------------------------------------
__global__ __launch_bounds__(256) void pack_adj_kernel(const void* __restrict__ adj_raw)
{
    int w = blockIdx.x * blockDim.x + threadIdx.x;   // word index
    unsigned bits = 0;
    if (g_adj_mode <= 1) {
        const int4* p = (const int4*)adj_raw + (size_t)w * 8;
        #pragma unroll
        for (int t = 0; t < 8; t++) {
            int4 v = p[t];
            bits |= (unsigned)(v.x != 0) << (t*4 + 0);
            bits |= (unsigned)(v.y != 0) << (t*4 + 1);
            bits |= (unsigned)(v.z != 0) << (t*4 + 2);
            bits |= (unsigned)(v.w != 0) << (t*4 + 3);
        }
    } else {
        const uint8_t* p = (const uint8_t*)adj_raw + (size_t)w * 32;
        #pragma unroll
        for (int j = 0; j < 32; j++)
            bits |= (unsigned)(p[j] != 0) << j;
    }
    g_adjbits[w] = bits;
}

// ---------------------------------------------------------------------------
// Projection via tf32 mma (2-mma compensated: X split hi/lo, W tf32-rounded).
// grid: (8192/128, 256/64, 3)  block: 256
// ---------------------------------------------------------------------------
__global__ __launch_bounds__(256, 2) void proj_kernel(
    const float* __restrict__ X,
    const float* __restrict__ Wq, const float* __restrict__ bq,
    const float* __restrict__ Wk, const float* __restrict__ bk,
    const float* __restrict__ Wv, const float* __restrict__ bv)
{
    const float* __restrict__ W;
    const float* __restrict__ bias;
    if (blockIdx.z == 0)      { W = Wq; bias = bq; }
    else if (blockIdx.z == 1) { W = Wk; bias = bk; }
    else                      { W = Wv; bias = bv; }

    __shared__ float    sX[128 * 36];   // fp32 X chunk, stride 36
    __shared__ uint32_t sW[2048];       // tf32 W chunk, fragment order

    const int tid  = threadIdx.x;
    const int warp = tid >> 5;
    const int lane = tid & 31;
    const int grp  = lane >> 2;
    const int tig  = lane & 3;
    const int m0   = blockIdx.x * 128;
    const int e0   = blockIdx.y * 64;
    const int prow0 = warp * 16 + grp;
    const int prow1 = prow0 + 8;

    float acc[8][4] = {};

    for (int kb = 0; kb < 8; kb++) {
        const int k0 = kb * 32;
        #pragma unroll
        for (int t = 0; t < 4; t++) {
            int f4 = tid + t * 256;
            int r  = f4 >> 3;
            int c  = (f4 & 7) << 2;
            float4 xv = *(const float4*)(X + (size_t)(m0 + r) * E_ + k0 + c);
            float* p = sX + r * 36 + c;
            p[0] = xv.x; p[1] = xv.y; p[2] = xv.z; p[3] = xv.w;
        }
        #pragma unroll
        for (int t = 0; t < 2; t++) {
            int f4 = tid + t * 256;
            int r  = f4 >> 3;
            int c  = (f4 & 7) << 2;
            float4 wv = *(const float4*)(W + (size_t)(e0 + r) * E_ + k0 + c);
            int base = ((r >> 3) * 4 + (c >> 3)) * 32 + (r & 7) * 4;
            int hf   = (c >> 2) & 1;
            sW[(base + 0) * 2 + hf] = f2tf32(wv.x);
            sW[(base + 1) * 2 + hf] = f2tf32(wv.y);
            sW[(base + 2) * 2 + hf] = f2tf32(wv.z);
            sW[(base + 3) * 2 + hf] = f2tf32(wv.w);
        }
        __syncthreads();

        #pragma unroll
        for (int kc = 0; kc < 4; kc++) {
            uint32_t xh[4], xl[4];
            #pragma unroll
            for (int i = 0; i < 4; i++) {
                int row = (i & 1) ? prow1 : prow0;
                int col = kc*8 + tig + ((i >> 1) << 2);
                float x = sX[row * 36 + col];
                xh[i] = f2tf32(x);
                xl[i] = f2tf32(x - __uint_as_float(xh[i]));
            }
            #pragma unroll
            for (int nt = 0; nt < 8; nt++) {
                uint2 w = ((const uint2*)sW)[(nt*4 + kc)*32 + lane];
                mma_tf32(acc[nt], xh, w.x, w.y);
                mma_tf32(acc[nt], xl, w.x, w.y);
            }
        }
        __syncthreads();
    }

    #pragma unroll
    for (int nt = 0; nt < 8; nt++) {
        int e = e0 + nt*8 + tig*2;           // even
        float2 bb = *(const float2*)(bias + e);
        int hh = e >> 5;
        int d  = e & 31;
        #pragma unroll
        for (int half = 0; half < 2; half++) {
            int m = m0 + (half ? prow1 : prow0);
            int b = m >> 12;
            int n = m & (N_ - 1);
            size_t bh = (size_t)(b*H_ + hh) * N_ * HS_;
            float v0 = acc[nt][half*2 + 0] + bb.x;
            float v1 = acc[nt][half*2 + 1] + bb.y;
            if (blockIdx.z == 0) {
                *(float2*)(g_Q + bh + (size_t)n * HS_ + d) = make_float2(v0, v1);
            } else if (blockIdx.z == 1) {
                int tile = n >> 6, r = n & 63;
                int i0 = (((r >> 3) * 4 + (d >> 3)) * 32 + (r & 7) * 4 + (d & 3)) * 2
                       + ((d >> 2) & 1);
                g_K[bh + tile * 2048 + i0]     = __uint_as_float(f2tf32(v0));
                g_K[bh + tile * 2048 + i0 + 2] = __uint_as_float(f2tf32(v1));
            } else {
                int tile = n >> 6, r = n & 63;
                int rl = r & 7;
                int p  = (r & 56) | ((rl >> 1) | ((rl & 1) << 2));
                int i0 = (((p >> 3) * 4 + (d >> 3)) * 32 + (d & 7) * 4 + (p & 3)) * 2
                       + ((p >> 2) & 1);
                g_V[bh + tile * 2048 + i0]     = __uint_as_float(f2tf32(v0));
                g_V[bh + tile * 2048 + i0 + 8] = __uint_as_float(f2tf32(v1));
            }
        }
    }
}

// ---------------------------------------------------------------------------
// Attention: 4 warps, 32 query rows per warp (two 16-row m-blocks). nt
// processed in PAIRS (16 independent QK mma -> 16 ex2 -> 16 PV mma) so the
// MUFU/cvt block of one nt overlaps the tensor work of its partner.
// __launch_bounds__(128, 3): reg cap ~170 gives ptxas room to pipeline.
// No-max softmax (S bounded), per-lane l, one reduction at the end.
// Double-buffered cp.async staging of fragment-ordered K/V.
// grid: (N/128, B*H)  block: 128
// smem: uint32[8192] = 32 KB. buf s: K at s*4096, V at s*4096+2048.
// ---------------------------------------------------------------------------
#define BM 128
#define BN 64

__global__ __launch_bounds__(128, 3) void attn_kernel(float* __restrict__ out)
{
    __shared__ uint32_t sm[8192];

    const int tid  = threadIdx.x;
    const int warp = tid >> 5;
    const int lane = tid & 31;
    const int grp  = lane >> 2;    // 0..7
    const int tig  = lane & 3;     // 0..3
    const int bh   = blockIdx.y;
    const int b    = bh >> 3;
    const int h    = bh & 7;
    const int n0   = blockIdx.x * BM;

    const float* __restrict__ Qg = g_Q + (size_t)bh * N_ * HS_;
    const float* __restrict__ Kg = g_K + (size_t)bh * N_ * HS_;   // fragment order
    const float* __restrict__ Vg = g_V + (size_t)bh * N_ * HS_;   // fragment order
    const unsigned* __restrict__ abase = g_adjbits + (size_t)b * N_ * NW_;

    const float qscale = 0.2550323215637855f;   // log2(e)/sqrt(HS)

    // ---- stage Q (scaled) into smem (stride 32) ----
    #pragma unroll
    for (int t = 0; t < 8; t++) {
        int f4 = tid + t * 128;           // 1024 float4
        int r  = f4 >> 3;
        int c  = (f4 & 7) << 2;
        float4 v = *(const float4*)(Qg + (size_t)(n0 + r) * HS_ + c);
        float* qs = (float*)sm + r * 32 + c;
        qs[0] = v.x * qscale; qs[1] = v.y * qscale;
        qs[2] = v.z * qscale; qs[3] = v.w * qscale;
    }
    __syncthreads();

    // warp owns rows [warp*32, warp*32+32): m-block 0 rows prow0, prow0+8;
    // m-block 1 rows prow0+16, prow0+24.
    const int prow0 = warp * 32 + grp;

    uint32_t qh0[4][4], qh1[4][4];
    #pragma unroll
    for (int kc = 0; kc < 4; kc++) {
        #pragma unroll
        for (int i = 0; i < 4; i++) {
            int col = kc*8 + tig + ((i >> 1) << 2);
            int roff = (i & 1) ? 8 : 0;
            qh0[kc][i] = f2tf32(((float*)sm)[(prow0 + roff)      * 32 + col]);
            qh1[kc][i] = f2tf32(((float*)sm)[(prow0 + 16 + roff) * 32 + col]);
        }
    }
    __syncthreads();   // smem becomes the K/V double buffer

    const uint32_t smbase = (uint32_t)__cvta_generic_to_shared(sm);

    // hoisted staging bases
    const float* ksb = Kg + tid * 16;
    const float* vsb = Vg + tid * 16;
    const uint32_t kd0 = smbase + tid * 64;

    // async-copy one 64-row tile (K 2048 + V 2048 words) into buffer s
    auto issue_tile = [&](int t, int s) {
        const float* ks = ksb + t * 2048;
        const float* vs = vsb + t * 2048;
        uint32_t kd = kd0 + s * 16384;
        CP_ASYNC16(kd,        ks);
        CP_ASYNC16(kd + 16,   ks + 4);
        CP_ASYNC16(kd + 32,   ks + 8);
        CP_ASYNC16(kd + 48,   ks + 12);
        CP_ASYNC16(kd + 8192, vs);
        CP_ASYNC16(kd + 8208, vs + 4);
        CP_ASYNC16(kd + 8224, vs + 8);
        CP_ASYNC16(kd + 8240, vs + 12);
        CP_COMMIT();
    };

    issue_tile(0, 0);
    issue_tile(1, 1);

    float l0a = 0.0f, l1a = 0.0f, l0b = 0.0f, l1b = 0.0f;
    float o0[4][4] = {};   // m-block 0 output, C-fragment layout
    float o1[4][4] = {};   // m-block 1

    const unsigned FULL = 0xffffffffu;

    for (int it = 0; it < N_ / BN; it++) {
        const int kv0 = it * BN;
        const int s   = it & 1;
        const uint2* KF = (const uint2*)(sm + s * 4096);
        const uint2* VF = KF + 1024;

        // adjacency words for this warp's 4 rows (2 words each)
        const unsigned* ar = abase + (size_t)(n0 + prow0) * NW_ + (kv0 >> 5);
        unsigned awa0 = ar[0],            awa1 = ar[1];               // row prow0
        unsigned awb0 = ar[8*NW_],        awb1 = ar[8*NW_ + 1];       // +8
        unsigned awc0 = ar[16*NW_],       awc1 = ar[16*NW_ + 1];      // +16
        unsigned awd0 = ar[24*NW_],       awd1 = ar[24*NW_ + 1];      // +24

        CP_WAIT(1);          // tile `it` landed (tile it+1 may still be in flight)
        __syncthreads();

        // --- nt PAIRS: 16 QK mma -> 16 masked ex2 -> 16 PV mma ---
        #pragma unroll
        for (int ntp = 0; ntp < 4; ntp++) {
            const int ntA = ntp * 2, ntB = ntA + 1;
            float sA0[4] = {}, sA1[4] = {}, sB0[4] = {}, sB1[4] = {};
            #pragma unroll
            for (int kc = 0; kc < 4; kc++) {
                uint2 kA = KF[(ntA*4 + kc)*32 + lane];
                uint2 kB = KF[(ntB*4 + kc)*32 + lane];
                mma_tf32(sA0, qh0[kc], kA.x, kA.y);
                mma_tf32(sB0, qh0[kc], kB.x, kB.y);
                mma_tf32(sA1, qh1[kc], kA.x, kA.y);
                mma_tf32(sB1, qh1[kc], kB.x, kB.y);
            }

            const int cA = ntA*8 + tig*2;
            const int cB = ntB*8 + tig*2;
            const int shA = cA & 31, shB = cB & 31;
            unsigned waA = (cA & 32) ? awa1 : awa0, waB = (cB & 32) ? awa1 : awa0;
            unsigned wbA = (cA & 32) ? awb1 : awb0, wbB = (cB & 32) ? awb1 : awb0;
            unsigned wcA = (cA & 32) ? awc1 : awc0, wcB = (cB & 32) ? awc1 : awc0;
            unsigned wdA = (cA & 32) ? awd1 : awd0, wdB = (cB & 32) ? awd1 : awd0;

            sA0[0] = ex2(((waA >> shA)     & 1) ? sA0[0] : -1e30f);
            sA0[1] = ex2(((waA >> (shA+1)) & 1) ? sA0[1] : -1e30f);
            sA0[2] = ex2(((wbA >> shA)     & 1) ? sA0[2] : -1e30f);
            sA0[3] = ex2(((wbA >> (shA+1)) & 1) ? sA0[3] : -1e30f);
            sA1[0] = ex2(((wcA >> shA)     & 1) ? sA1[0] : -1e30f);
            sA1[1] = ex2(((wcA >> (shA+1)) & 1) ? sA1[1] : -1e30f);
            sA1[2] = ex2(((wdA >> shA)     & 1) ? sA1[2] : -1e30f);
            sA1[3] = ex2(((wdA >> (shA+1)) & 1) ? sA1[3] : -1e30f);
            sB0[0] = ex2(((waB >> shB)     & 1) ? sB0[0] : -1e30f);
            sB0[1] = ex2(((waB >> (shB+1)) & 1) ? sB0[1] : -1e30f);
            sB0[2] = ex2(((wbB >> shB)     & 1) ? sB0[2] : -1e30f);
            sB0[3] = ex2(((wbB >> (shB+1)) & 1) ? sB0[3] : -1e30f);
            sB1[0] = ex2(((wcB >> shB)     & 1) ? sB1[0] : -1e30f);
            sB1[1] = ex2(((wcB >> (shB+1)) & 1) ? sB1[1] : -1e30f);
            sB1[2] = ex2(((wdB >> shB)     & 1) ? sB1[2] : -1e30f);
            sB1[3] = ex2(((wdB >> (shB+1)) & 1) ? sB1[3] : -1e30f);

            uint32_t aA0[4], aA1[4], aB0[4], aB1[4];
            aA0[0] = f2tf32(sA0[0]); aA0[1] = f2tf32(sA0[2]);
            aA0[2] = f2tf32(sA0[1]); aA0[3] = f2tf32(sA0[3]);
            aA1[0] = f2tf32(sA1[0]); aA1[1] = f2tf32(sA1[2]);
            aA1[2] = f2tf32(sA1[1]); aA1[3] = f2tf32(sA1[3]);
            aB0[0] = f2tf32(sB0[0]); aB0[1] = f2tf32(sB0[2]);
            aB0[2] = f2tf32(sB0[1]); aB0[3] = f2tf32(sB0[3]);
            aB1[0] = f2tf32(sB1[0]); aB1[1] = f2tf32(sB1[2]);
            aB1[2] = f2tf32(sB1[1]); aB1[3] = f2tf32(sB1[3]);

            l0a += __uint_as_float(aA0[0]) + __uint_as_float(aA0[2]);
            l1a += __uint_as_float(aA0[1]) + __uint_as_float(aA0[3]);
            l0b += __uint_as_float(aA1[0]) + __uint_as_float(aA1[2]);
            l1b += __uint_as_float(aA1[1]) + __uint_as_float(aA1[3]);
            l0a += __uint_as_float(aB0[0]) + __uint_as_float(aB0[2]);
            l1a += __uint_as_float(aB0[1]) + __uint_as_float(aB0[3]);
            l0b += __uint_as_float(aB1[0]) + __uint_as_float(aB1[2]);
            l1b += __uint_as_float(aB1[1]) + __uint_as_float(aB1[3]);

            #pragma unroll
            for (int nt4 = 0; nt4 < 4; nt4++) {
                uint2 vA = VF[(ntA*4 + nt4)*32 + lane];
                uint2 vB = VF[(ntB*4 + nt4)*32 + lane];
                mma_tf32(o0[nt4], aA0, vA.x, vA.y);
                mma_tf32(o1[nt4], aA1, vA.x, vA.y);
                mma_tf32(o0[nt4], aB0, vB.x, vB.y);
                mma_tf32(o1[nt4], aB1, vB.x, vB.y);
            }
        }
        __syncthreads();     // all warps done with buffer s

        if (it + 2 < N_ / BN)
            issue_tile(it + 2, s);   // refill the buffer just freed
    }

    // --- single deferred l reduction across the 4 tig lanes ---
    l0a += __shfl_xor_sync(FULL, l0a, 1); l0a += __shfl_xor_sync(FULL, l0a, 2);
    l1a += __shfl_xor_sync(FULL, l1a, 1); l1a += __shfl_xor_sync(FULL, l1a, 2);
    l0b += __shfl_xor_sync(FULL, l0b, 1); l0b += __shfl_xor_sync(FULL, l0b, 2);
    l1b += __shfl_xor_sync(FULL, l1b, 1); l1b += __shfl_xor_sync(FULL, l1b, 2);

    // --- finalize ---
    float i0a = 1.0f / l0a, i1a = 1.0f / l1a;
    float i0b = 1.0f / l0b, i1b = 1.0f / l1b;
    #pragma unroll
    for (int nt4 = 0; nt4 < 4; nt4++) {
        int col = h * HS_ + nt4*8 + tig*2;
        *(float2*)(out + ((size_t)(b * N_ + n0 + prow0))      * E_ + col) =
            make_float2(o0[nt4][0] * i0a, o0[nt4][1] * i0a);
        *(float2*)(out + ((size_t)(b * N_ + n0 + prow0 + 8))  * E_ + col) =
            make_float2(o0[nt4][2] * i1a, o0[nt4][3] * i1a);
        *(float2*)(out + ((size_t)(b * N_ + n0 + prow0 + 16)) * E_ + col) =
            make_float2(o1[nt4][0] * i0b, o1[nt4][1] * i0b);
        *(float2*)(out + ((size_t)(b * N_ + n0 + prow0 + 24)) * E_ + col) =
            make_float2(o1[nt4][2] * i1b, o1[nt4][3] * i1b);
    }
}

// ---------------------------------------------------------------------------
extern "C" void kernel_launch(void* const* d_in, const int* in_sizes, int n_in,
                              void* d_out, int out_size)
{
    const float* X   = (const float*)d_in[0];
    const void*  adj = d_in[1];
    const float* Wq  = (const float*)d_in[2];
    const float* bq  = (const float*)d_in[3];
    const float* Wk  = (const float*)d_in[4];
    const float* bk  = (const float*)d_in[5];
    const float* Wv  = (const float*)d_in[6];
    const float* bv  = (const float*)d_in[7];
    float*       out = (float*)d_out;

    detect_adj_kernel<<<1, 256>>>((const unsigned*)adj);

    pack_adj_kernel<<<(B_ * N_ * NW_) / 256, 256>>>(adj);

    dim3 pg(B_ * N_ / 128, E_ / 64, 3);
    proj_kernel<<<pg, 256>>>(X, Wq, bq, Wk, bk, Wv, bv);

    dim3 ag(N_ / BM, BHTOT);
    attn_kernel<<<ag, 128>>>(out);
}

// round 14
// speedup vs baseline: 1.1095x; 1.1095x over previous
#include <cuda_runtime.h>
#include <stdint.h>

#define B_   2
#define N_   4096
#define E_   256
#define H_   8
#define HS_  32
#define BHTOT (B_*H_)
#define NW_  (N_/32)          // adj bitmask words per row

// Scratch:
//  g_Q : fp32 [B,H,N,HS]
//  g_K : tf32-rounded, FRAGMENT ORDER per (bh, 64-row tile)
//  g_V : tf32-rounded, fragment order with PV row permutation baked in
__device__ float    g_Q[(size_t)BHTOT * N_ * HS_];
__device__ float    g_K[(size_t)BHTOT * N_ * HS_];
__device__ float    g_V[(size_t)BHTOT * N_ * HS_];
__device__ unsigned g_adjbits[(size_t)B_ * N_ * NW_];
__device__ int      g_adj_mode;   // 0=int32{0,1}, 1=float32{0,1.0f}, 2=uint8{0,1}

// ---------------------------------------------------------------------------
// helpers
// ---------------------------------------------------------------------------
__device__ __forceinline__ uint32_t f2tf32(float f) {
    uint32_t r;
    asm("cvt.rna.tf32.f32 %0, %1;" : "=r"(r) : "f"(f));
    return r;
}
__device__ __forceinline__ float ex2(float x) {
    float r;
    asm("ex2.approx.f32 %0, %1;" : "=f"(r) : "f"(x));
    return r;
}
__device__ __forceinline__ void mma_tf32(float c[4], const uint32_t a[4],
                                         uint32_t b0, uint32_t b1) {
    asm volatile(
        "mma.sync.aligned.m16n8k8.row.col.f32.tf32.tf32.f32 "
        "{%0,%1,%2,%3}, {%4,%5,%6,%7}, {%8,%9}, {%0,%1,%2,%3};\n"
        : "+f"(c[0]), "+f"(c[1]), "+f"(c[2]), "+f"(c[3])
        : "r"(a[0]), "r"(a[1]), "r"(a[2]), "r"(a[3]), "r"(b0), "r"(b1));
}
#define CP_ASYNC16(dst_u32, src_ptr) \
    asm volatile("cp.async.ca.shared.global [%0], [%1], 16;\n" \
                 :: "r"(dst_u32), "l"(src_ptr))
#define CP_COMMIT() asm volatile("cp.async.commit_group;\n")
#define CP_WAIT(n)  asm volatile("cp.async.wait_group %0;\n" :: "n"(n))

// ---------------------------------------------------------------------------
// Detect adjacency storage dtype from bit patterns (deterministic, 64 KB scan).
// ---------------------------------------------------------------------------
__global__ __launch_bounds__(256) void detect_adj_kernel(const unsigned* __restrict__ a)
{
    __shared__ int s_ok[2];
    if (threadIdx.x == 0) { s_ok[0] = 1; s_ok[1] = 1; }
    __syncthreads();
    int ok_i = 1, ok_f = 1;
    for (int i = threadIdx.x; i < (1 << 14); i += 256) {
        unsigned w = a[i];
        if (w != 0u && w != 1u)          ok_i = 0;
        if (w != 0u && w != 0x3F800000u) ok_f = 0;
    }
    if (!ok_i) atomicAnd(&s_ok[0], 0);
    if (!ok_f) atomicAnd(&s_ok[1], 0);
    __syncthreads();
    if (threadIdx.x == 0) g_adj_mode = s_ok[0] ? 0 : (s_ok[1] ? 1 : 2);
}

// ---------------------------------------------------------------------------
// Pack adjacency to bitmask: g_adjbits[b*N + n][w] bit j = adj[b][n][w*32+j]
// ---------------------------------------------------------------------------
__global__ __launch_bounds__(256) void pack_adj_kernel(const void* __restrict__ adj_raw)
{
    int w = blockIdx.x * blockDim.x + threadIdx.x;   // word index
    unsigned bits = 0;
    if (g_adj_mode <= 1) {
        const int4* p = (const int4*)adj_raw + (size_t)w * 8;
        #pragma unroll
        for (int t = 0; t < 8; t++) {
            int4 v = p[t];
            bits |= (unsigned)(v.x != 0) << (t*4 + 0);
            bits |= (unsigned)(v.y != 0) << (t*4 + 1);
            bits |= (unsigned)(v.z != 0) << (t*4 + 2);
            bits |= (unsigned)(v.w != 0) << (t*4 + 3);
        }
    } else {
        const uint8_t* p = (const uint8_t*)adj_raw + (size_t)w * 32;
        #pragma unroll
        for (int j = 0; j < 32; j++)
            bits |= (unsigned)(p[j] != 0) << j;
    }
    g_adjbits[w] = bits;
}

// ---------------------------------------------------------------------------
// Projection via tf32 mma (2-mma compensated: X split hi/lo, W tf32-rounded).
// grid: (8192/128, 256/64, 3)  block: 256
// ---------------------------------------------------------------------------
__global__ __launch_bounds__(256, 2) void proj_kernel(
    const float* __restrict__ X,
    const float* __restrict__ Wq, const float* __restrict__ bq,
    const float* __restrict__ Wk, const float* __restrict__ bk,
    const float* __restrict__ Wv, const float* __restrict__ bv)
{
    const float* __restrict__ W;
    const float* __restrict__ bias;
    if (blockIdx.z == 0)      { W = Wq; bias = bq; }
    else if (blockIdx.z == 1) { W = Wk; bias = bk; }
    else                      { W = Wv; bias = bv; }

    __shared__ float    sX[128 * 36];   // fp32 X chunk, stride 36
    __shared__ uint32_t sW[2048];       // tf32 W chunk, fragment order

    const int tid  = threadIdx.x;
    const int warp = tid >> 5;
    const int lane = tid & 31;
    const int grp  = lane >> 2;
    const int tig  = lane & 3;
    const int m0   = blockIdx.x * 128;
    const int e0   = blockIdx.y * 64;
    const int prow0 = warp * 16 + grp;
    const int prow1 = prow0 + 8;

    float acc[8][4] = {};

    for (int kb = 0; kb < 8; kb++) {
        const int k0 = kb * 32;
        #pragma unroll
        for (int t = 0; t < 4; t++) {
            int f4 = tid + t * 256;
            int r  = f4 >> 3;
            int c  = (f4 & 7) << 2;
            float4 xv = *(const float4*)(X + (size_t)(m0 + r) * E_ + k0 + c);
            float* p = sX + r * 36 + c;
            p[0] = xv.x; p[1] = xv.y; p[2] = xv.z; p[3] = xv.w;
        }
        #pragma unroll
        for (int t = 0; t < 2; t++) {
            int f4 = tid + t * 256;
            int r  = f4 >> 3;
            int c  = (f4 & 7) << 2;
            float4 wv = *(const float4*)(W + (size_t)(e0 + r) * E_ + k0 + c);
            int base = ((r >> 3) * 4 + (c >> 3)) * 32 + (r & 7) * 4;
            int hf   = (c >> 2) & 1;
            sW[(base + 0) * 2 + hf] = f2tf32(wv.x);
            sW[(base + 1) * 2 + hf] = f2tf32(wv.y);
            sW[(base + 2) * 2 + hf] = f2tf32(wv.z);
            sW[(base + 3) * 2 + hf] = f2tf32(wv.w);
        }
        __syncthreads();

        #pragma unroll
        for (int kc = 0; kc < 4; kc++) {
            uint32_t xh[4], xl[4];
            #pragma unroll
            for (int i = 0; i < 4; i++) {
                int row = (i & 1) ? prow1 : prow0;
                int col = kc*8 + tig + ((i >> 1) << 2);
                float x = sX[row * 36 + col];
                xh[i] = f2tf32(x);
                xl[i] = f2tf32(x - __uint_as_float(xh[i]));
            }
            #pragma unroll
            for (int nt = 0; nt < 8; nt++) {
                uint2 w = ((const uint2*)sW)[(nt*4 + kc)*32 + lane];
                mma_tf32(acc[nt], xh, w.x, w.y);
                mma_tf32(acc[nt], xl, w.x, w.y);
            }
        }
        __syncthreads();
    }

    #pragma unroll
    for (int nt = 0; nt < 8; nt++) {
        int e = e0 + nt*8 + tig*2;           // even
        float2 bb = *(const float2*)(bias + e);
        int hh = e >> 5;
        int d  = e & 31;
        #pragma unroll
        for (int half = 0; half < 2; half++) {
            int m = m0 + (half ? prow1 : prow0);
            int b = m >> 12;
            int n = m & (N_ - 1);
            size_t bh = (size_t)(b*H_ + hh) * N_ * HS_;
            float v0 = acc[nt][half*2 + 0] + bb.x;
            float v1 = acc[nt][half*2 + 1] + bb.y;
            if (blockIdx.z == 0) {
                *(float2*)(g_Q + bh + (size_t)n * HS_ + d) = make_float2(v0, v1);
            } else if (blockIdx.z == 1) {
                int tile = n >> 6, r = n & 63;
                int i0 = (((r >> 3) * 4 + (d >> 3)) * 32 + (r & 7) * 4 + (d & 3)) * 2
                       + ((d >> 2) & 1);
                g_K[bh + tile * 2048 + i0]     = __uint_as_float(f2tf32(v0));
                g_K[bh + tile * 2048 + i0 + 2] = __uint_as_float(f2tf32(v1));
            } else {
                int tile = n >> 6, r = n & 63;
                int rl = r & 7;
                int p  = (r & 56) | ((rl >> 1) | ((rl & 1) << 2));
                int i0 = (((p >> 3) * 4 + (d >> 3)) * 32 + (d & 7) * 4 + (p & 3)) * 2
                       + ((p >> 2) & 1);
                g_V[bh + tile * 2048 + i0]     = __uint_as_float(f2tf32(v0));
                g_V[bh + tile * 2048 + i0 + 8] = __uint_as_float(f2tf32(v1));
            }
        }
    }
}

// ---------------------------------------------------------------------------
// Attention (R12 math, 3-stage pipeline): 4 warps, 32 query rows per warp,
// fused per-nt pipeline (QK mma -> mask -> exp2 -> PV mma). THREE cp.async
// buffers with issue-BEFORE-compute: one __syncthreads per tile instead of
// two (the top-of-iteration sync already licenses refilling buffer
// (it+2)%3, consumed in iteration it-1). No-max softmax, per-lane l.
// grid: (N/128, B*H)  block: 128
// smem: uint32[12288] = 48 KB. buf s: K at s*4096, V at s*4096+2048.
// ---------------------------------------------------------------------------
#define BM 128
#define BN 64

__global__ __launch_bounds__(128, 4) void attn_kernel(float* __restrict__ out)
{
    __shared__ uint32_t sm[12288];

    const int tid  = threadIdx.x;
    const int warp = tid >> 5;
    const int lane = tid & 31;
    const int grp  = lane >> 2;    // 0..7
    const int tig  = lane & 3;     // 0..3
    const int bh   = blockIdx.y;
    const int b    = bh >> 3;
    const int h    = bh & 7;
    const int n0   = blockIdx.x * BM;

    const float* __restrict__ Qg = g_Q + (size_t)bh * N_ * HS_;
    const float* __restrict__ Kg = g_K + (size_t)bh * N_ * HS_;   // fragment order
    const float* __restrict__ Vg = g_V + (size_t)bh * N_ * HS_;   // fragment order
    const unsigned* __restrict__ abase = g_adjbits + (size_t)b * N_ * NW_;

    const float qscale = 0.2550323215637855f;   // log2(e)/sqrt(HS)

    // ---- stage Q (scaled) into smem (stride 32) ----
    #pragma unroll
    for (int t = 0; t < 8; t++) {
        int f4 = tid + t * 128;           // 1024 float4
        int r  = f4 >> 3;
        int c  = (f4 & 7) << 2;
        float4 v = *(const float4*)(Qg + (size_t)(n0 + r) * HS_ + c);
        float* qs = (float*)sm + r * 32 + c;
        qs[0] = v.x * qscale; qs[1] = v.y * qscale;
        qs[2] = v.z * qscale; qs[3] = v.w * qscale;
    }
    __syncthreads();

    // warp owns rows [warp*32, warp*32+32): m-block 0 rows prow0, prow0+8;
    // m-block 1 rows prow0+16, prow0+24.
    const int prow0 = warp * 32 + grp;

    uint32_t qh0[4][4], qh1[4][4];
    #pragma unroll
    for (int kc = 0; kc < 4; kc++) {
        #pragma unroll
        for (int i = 0; i < 4; i++) {
            int col = kc*8 + tig + ((i >> 1) << 2);
            int roff = (i & 1) ? 8 : 0;
            qh0[kc][i] = f2tf32(((float*)sm)[(prow0 + roff)      * 32 + col]);
            qh1[kc][i] = f2tf32(((float*)sm)[(prow0 + 16 + roff) * 32 + col]);
        }
    }
    __syncthreads();   // smem becomes the K/V triple buffer

    const uint32_t smbase = (uint32_t)__cvta_generic_to_shared(sm);

    // async-copy one 64-row tile (K 2048 + V 2048 words) into buffer t%3
    auto issue_tile = [&](int t) {
        const float* ks = Kg + t * 2048 + tid * 16;
        const float* vs = Vg + t * 2048 + tid * 16;
        uint32_t kd = smbase + (t % 3) * 16384 + tid * 64;
        CP_ASYNC16(kd,        ks);
        CP_ASYNC16(kd + 16,   ks + 4);
        CP_ASYNC16(kd + 32,   ks + 8);
        CP_ASYNC16(kd + 48,   ks + 12);
        CP_ASYNC16(kd + 8192, vs);
        CP_ASYNC16(kd + 8208, vs + 4);
        CP_ASYNC16(kd + 8224, vs + 8);
        CP_ASYNC16(kd + 8240, vs + 12);
        CP_COMMIT();
    };

    issue_tile(0);
    issue_tile(1);

    float l0a = 0.0f, l1a = 0.0f, l0b = 0.0f, l1b = 0.0f;
    float o0[4][4] = {};   // m-block 0 output, C-fragment layout
    float o1[4][4] = {};   // m-block 1

    const unsigned FULL = 0xffffffffu;

    for (int it = 0; it < N_ / BN; it++) {
        const int kv0 = it * BN;
        const uint2* KF = (const uint2*)(sm + (it % 3) * 4096);
        const uint2* VF = KF + 1024;

        // adjacency words for this warp's 4 rows (2 words each)
        const unsigned* ar = abase + (size_t)(n0 + prow0) * NW_ + (kv0 >> 5);
        unsigned awa0 = ar[0],            awa1 = ar[1];               // row prow0
        unsigned awb0 = ar[8*NW_],        awb1 = ar[8*NW_ + 1];       // +8
        unsigned awc0 = ar[16*NW_],       awc1 = ar[16*NW_ + 1];      // +16
        unsigned awd0 = ar[24*NW_],       awd1 = ar[24*NW_ + 1];      // +24

        CP_WAIT(1);          // tile `it` landed (tile it+1 may still be in flight)
        __syncthreads();     // also: every warp finished tile it-1 -> its buffer free

        if (it + 2 < N_ / BN)
            issue_tile(it + 2);   // refill buffer (it+2)%3, freed in iteration it-1

        // --- fused per-nt: QK (1-mma) -> mask -> exp2 -> PV ---
        #pragma unroll
        for (int nt = 0; nt < 8; nt++) {
            float s0[4] = {}, s1[4] = {};
            #pragma unroll
            for (int kc = 0; kc < 4; kc++) {
                uint2 k = KF[(nt*4 + kc)*32 + lane];
                mma_tf32(s0, qh0[kc], k.x, k.y);
                mma_tf32(s1, qh1[kc], k.x, k.y);
            }

            int c0 = nt*8 + tig*2;        // even; c0,c0+1 share a word
            int sh = c0 & 31;
            unsigned wa = (c0 & 32) ? awa1 : awa0;
            unsigned wb = (c0 & 32) ? awb1 : awb0;
            unsigned wc = (c0 & 32) ? awc1 : awc0;
            unsigned wd = (c0 & 32) ? awd1 : awd0;

            s0[0] = ex2(((wa >> sh)     & 1) ? s0[0] : -1e30f);
            s0[1] = ex2(((wa >> (sh+1)) & 1) ? s0[1] : -1e30f);
            s0[2] = ex2(((wb >> sh)     & 1) ? s0[2] : -1e30f);
            s0[3] = ex2(((wb >> (sh+1)) & 1) ? s0[3] : -1e30f);
            s1[0] = ex2(((wc >> sh)     & 1) ? s1[0] : -1e30f);
            s1[1] = ex2(((wc >> (sh+1)) & 1) ? s1[1] : -1e30f);
            s1[2] = ex2(((wd >> sh)     & 1) ? s1[2] : -1e30f);
            s1[3] = ex2(((wd >> (sh+1)) & 1) ? s1[3] : -1e30f);

            uint32_t a0[4], a1[4];
            a0[0] = f2tf32(s0[0]); a0[1] = f2tf32(s0[2]);
            a0[2] = f2tf32(s0[1]); a0[3] = f2tf32(s0[3]);
            a1[0] = f2tf32(s1[0]); a1[1] = f2tf32(s1[2]);
            a1[2] = f2tf32(s1[1]); a1[3] = f2tf32(s1[3]);
            l0a += __uint_as_float(a0[0]) + __uint_as_float(a0[2]);
            l1a += __uint_as_float(a0[1]) + __uint_as_float(a0[3]);
            l0b += __uint_as_float(a1[0]) + __uint_as_float(a1[2]);
            l1b += __uint_as_float(a1[1]) + __uint_as_float(a1[3]);

            #pragma unroll
            for (int nt4 = 0; nt4 < 4; nt4++) {
                uint2 v = VF[(nt*4 + nt4)*32 + lane];
                mma_tf32(o0[nt4], a0, v.x, v.y);
                mma_tf32(o1[nt4], a1, v.x, v.y);
            }
        }
        // no trailing sync: next iteration's top sync covers buffer reuse
    }

    // --- single deferred l reduction across the 4 tig lanes ---
    l0a += __shfl_xor_sync(FULL, l0a, 1); l0a += __shfl_xor_sync(FULL, l0a, 2);
    l1a += __shfl_xor_sync(FULL, l1a, 1); l1a += __shfl_xor_sync(FULL, l1a, 2);
    l0b += __shfl_xor_sync(FULL, l0b, 1); l0b += __shfl_xor_sync(FULL, l0b, 2);
    l1b += __shfl_xor_sync(FULL, l1b, 1); l1b += __shfl_xor_sync(FULL, l1b, 2);

    // --- finalize ---
    float i0a = 1.0f / l0a, i1a = 1.0f / l1a;
    float i0b = 1.0f / l0b, i1b = 1.0f / l1b;
    #pragma unroll
    for (int nt4 = 0; nt4 < 4; nt4++) {
        int col = h * HS_ + nt4*8 + tig*2;
        *(float2*)(out + ((size_t)(b * N_ + n0 + prow0))      * E_ + col) =
            make_float2(o0[nt4][0] * i0a, o0[nt4][1] * i0a);
        *(float2*)(out + ((size_t)(b * N_ + n0 + prow0 + 8))  * E_ + col) =
            make_float2(o0[nt4][2] * i1a, o0[nt4][3] * i1a);
        *(float2*)(out + ((size_t)(b * N_ + n0 + prow0 + 16)) * E_ + col) =
            make_float2(o1[nt4][0] * i0b, o1[nt4][1] * i0b);
        *(float2*)(out + ((size_t)(b * N_ + n0 + prow0 + 24)) * E_ + col) =
            make_float2(o1[nt4][2] * i1b, o1[nt4][3] * i1b);
    }
}

// ---------------------------------------------------------------------------
extern "C" void kernel_launch(void* const* d_in, const int* in_sizes, int n_in,
                              void* d_out, int out_size)
{
    const float* X   = (const float*)d_in[0];
    const void*  adj = d_in[1];
    const float* Wq  = (const float*)d_in[2];
    const float* bq  = (const float*)d_in[3];
    const float* Wk  = (const float*)d_in[4];
    const float* bk  = (const float*)d_in[5];
    const float* Wv  = (const float*)d_in[6];
    const float* bv  = (const float*)d_in[7];
    float*       out = (float*)d_out;

    detect_adj_kernel<<<1, 256>>>((const unsigned*)adj);

    pack_adj_kernel<<<(B_ * N_ * NW_) / 256, 256>>>(adj);

    dim3 pg(B_ * N_ / 128, E_ / 64, 3);
    proj_kernel<<<pg, 256>>>(X, Wq, bq, Wk, bk, Wv, bv);

    dim3 ag(N_ / BM, BHTOT);
    attn_kernel<<<ag, 128>>>(out);
}

// round 15
// speedup vs baseline: 1.1598x; 1.0453x over previous
#include <cuda_runtime.h>
#include <stdint.h>

#define B_   2
#define N_   4096
#define E_   256
#define H_   8
#define HS_  32
#define BHTOT (B_*H_)
#define NW_  (N_/32)          // adj bitmask words per row

// Scratch:
//  g_Q : fp32 [B,H,N,HS]
//  g_K : tf32-rounded, FRAGMENT-PAIR order (uint4/lane) per (bh, 64-row tile)
//  g_V : tf32-rounded, fragment-pair order with PV row permutation baked in
__device__ float    g_Q[(size_t)BHTOT * N_ * HS_];
__device__ float    g_K[(size_t)BHTOT * N_ * HS_];
__device__ float    g_V[(size_t)BHTOT * N_ * HS_];
__device__ unsigned g_adjbits[(size_t)B_ * N_ * NW_];
__device__ int      g_adj_mode;   // 0=int32{0,1}, 1=float32{0,1.0f}, 2=uint8{0,1}

// ---------------------------------------------------------------------------
// helpers
// ---------------------------------------------------------------------------
__device__ __forceinline__ uint32_t f2tf32(float f) {
    uint32_t r;
    asm("cvt.rna.tf32.f32 %0, %1;" : "=r"(r) : "f"(f));
    return r;
}
__device__ __forceinline__ float ex2(float x) {
    float r;
    asm("ex2.approx.f32 %0, %1;" : "=f"(r) : "f"(x));
    return r;
}
__device__ __forceinline__ void mma_tf32(float c[4], const uint32_t a[4],
                                         uint32_t b0, uint32_t b1) {
    asm volatile(
        "mma.sync.aligned.m16n8k8.row.col.f32.tf32.tf32.f32 "
        "{%0,%1,%2,%3}, {%4,%5,%6,%7}, {%8,%9}, {%0,%1,%2,%3};\n"
        : "+f"(c[0]), "+f"(c[1]), "+f"(c[2]), "+f"(c[3])
        : "r"(a[0]), "r"(a[1]), "r"(a[2]), "r"(a[3]), "r"(b0), "r"(b1));
}
#define CP_ASYNC16(dst_u32, src_ptr) \
    asm volatile("cp.async.ca.shared.global [%0], [%1], 16;\n" \
                 :: "r"(dst_u32), "l"(src_ptr))
#define CP_COMMIT() asm volatile("cp.async.commit_group;\n")
#define CP_WAIT(n)  asm volatile("cp.async.wait_group %0;\n" :: "n"(n))

// ---------------------------------------------------------------------------
// Detect adjacency storage dtype from bit patterns (deterministic, 64 KB scan).
// ---------------------------------------------------------------------------
__global__ __launch_bounds__(256) void detect_adj_kernel(const unsigned* __restrict__ a)
{
    __shared__ int s_ok[2];
    if (threadIdx.x == 0) { s_ok[0] = 1; s_ok[1] = 1; }
    __syncthreads();
    int ok_i = 1, ok_f = 1;
    for (int i = threadIdx.x; i < (1 << 14); i += 256) {
        unsigned w = a[i];
        if (w != 0u && w != 1u)          ok_i = 0;
        if (w != 0u && w != 0x3F800000u) ok_f = 0;
    }
    if (!ok_i) atomicAnd(&s_ok[0], 0);
    if (!ok_f) atomicAnd(&s_ok[1], 0);
    __syncthreads();
    if (threadIdx.x == 0) g_adj_mode = s_ok[0] ? 0 : (s_ok[1] ? 1 : 2);
}

// ---------------------------------------------------------------------------
// Pack adjacency to bitmask: g_adjbits[b*N + n][w] bit j = adj[b][n][w*32+j]
// ---------------------------------------------------------------------------
__global__ __launch_bounds__(256) void pack_adj_kernel(const void* __restrict__ adj_raw)
{
    int w = blockIdx.x * blockDim.x + threadIdx.x;   // word index
    unsigned bits = 0;
    if (g_adj_mode <= 1) {
        const int4* p = (const int4*)adj_raw + (size_t)w * 8;
        #pragma unroll
        for (int t = 0; t < 8; t++) {
            int4 v = p[t];
            bits |= (unsigned)(v.x != 0) << (t*4 + 0);
            bits |= (unsigned)(v.y != 0) << (t*4 + 1);
            bits |= (unsigned)(v.z != 0) << (t*4 + 2);
            bits |= (unsigned)(v.w != 0) << (t*4 + 3);
        }
    } else {
        const uint8_t* p = (const uint8_t*)adj_raw + (size_t)w * 32;
        #pragma unroll
        for (int j = 0; j < 32; j++)
            bits |= (unsigned)(p[j] != 0) << j;
    }
    g_adjbits[w] = bits;
}

// ---------------------------------------------------------------------------
// Projection via tf32 mma (2-mma compensated: X split hi/lo, W tf32-rounded).
// K scatter: fragment-PAIR order (uint4 per lane, kc pairs interleaved):
//   (r,d): nt=r>>3, kcp=d>>4, sub=(d>>3)&1, half=(d>>2)&1, lane=(r&7)*4+(d&3)
//   idx = ((nt*2+kcp)*32 + lane)*4 + sub*2 + half
// V scatter (rows PV-permuted): (p,d): kc=p>>3, nt4p=d>>4, sub=(d>>3)&1,
//   half=(p>>2)&1, lane=(d&7)*4+(p&3); idx = ((kc*2+nt4p)*32+lane)*4+sub*2+half
// grid: (8192/128, 256/64, 3)  block: 256
// ---------------------------------------------------------------------------
__global__ __launch_bounds__(256, 2) void proj_kernel(
    const float* __restrict__ X,
    const float* __restrict__ Wq, const float* __restrict__ bq,
    const float* __restrict__ Wk, const float* __restrict__ bk,
    const float* __restrict__ Wv, const float* __restrict__ bv)
{
    const float* __restrict__ W;
    const float* __restrict__ bias;
    if (blockIdx.z == 0)      { W = Wq; bias = bq; }
    else if (blockIdx.z == 1) { W = Wk; bias = bk; }
    else                      { W = Wv; bias = bv; }

    __shared__ float    sX[128 * 36];   // fp32 X chunk, stride 36
    __shared__ uint32_t sW[2048];       // tf32 W chunk, fragment order

    const int tid  = threadIdx.x;
    const int warp = tid >> 5;
    const int lane = tid & 31;
    const int grp  = lane >> 2;
    const int tig  = lane & 3;
    const int m0   = blockIdx.x * 128;
    const int e0   = blockIdx.y * 64;
    const int prow0 = warp * 16 + grp;
    const int prow1 = prow0 + 8;

    float acc[8][4] = {};

    for (int kb = 0; kb < 8; kb++) {
        const int k0 = kb * 32;
        #pragma unroll
        for (int t = 0; t < 4; t++) {
            int f4 = tid + t * 256;
            int r  = f4 >> 3;
            int c  = (f4 & 7) << 2;
            float4 xv = *(const float4*)(X + (size_t)(m0 + r) * E_ + k0 + c);
            float* p = sX + r * 36 + c;
            p[0] = xv.x; p[1] = xv.y; p[2] = xv.z; p[3] = xv.w;
        }
        #pragma unroll
        for (int t = 0; t < 2; t++) {
            int f4 = tid + t * 256;
            int r  = f4 >> 3;
            int c  = (f4 & 7) << 2;
            float4 wv = *(const float4*)(W + (size_t)(e0 + r) * E_ + k0 + c);
            int base = ((r >> 3) * 4 + (c >> 3)) * 32 + (r & 7) * 4;
            int hf   = (c >> 2) & 1;
            sW[(base + 0) * 2 + hf] = f2tf32(wv.x);
            sW[(base + 1) * 2 + hf] = f2tf32(wv.y);
            sW[(base + 2) * 2 + hf] = f2tf32(wv.z);
            sW[(base + 3) * 2 + hf] = f2tf32(wv.w);
        }
        __syncthreads();

        #pragma unroll
        for (int kc = 0; kc < 4; kc++) {
            uint32_t xh[4], xl[4];
            #pragma unroll
            for (int i = 0; i < 4; i++) {
                int row = (i & 1) ? prow1 : prow0;
                int col = kc*8 + tig + ((i >> 1) << 2);
                float x = sX[row * 36 + col];
                xh[i] = f2tf32(x);
                xl[i] = f2tf32(x - __uint_as_float(xh[i]));
            }
            #pragma unroll
            for (int nt = 0; nt < 8; nt++) {
                uint2 w = ((const uint2*)sW)[(nt*4 + kc)*32 + lane];
                mma_tf32(acc[nt], xh, w.x, w.y);
                mma_tf32(acc[nt], xl, w.x, w.y);
            }
        }
        __syncthreads();
    }

    #pragma unroll
    for (int nt = 0; nt < 8; nt++) {
        int e = e0 + nt*8 + tig*2;           // even
        float2 bb = *(const float2*)(bias + e);
        int hh = e >> 5;
        int d  = e & 31;
        #pragma unroll
        for (int half = 0; half < 2; half++) {
            int m = m0 + (half ? prow1 : prow0);
            int b = m >> 12;
            int n = m & (N_ - 1);
            size_t bh = (size_t)(b*H_ + hh) * N_ * HS_;
            float v0 = acc[nt][half*2 + 0] + bb.x;
            float v1 = acc[nt][half*2 + 1] + bb.y;
            if (blockIdx.z == 0) {
                *(float2*)(g_Q + bh + (size_t)n * HS_ + d) = make_float2(v0, v1);
            } else if (blockIdx.z == 1) {
                int tile = n >> 6, r = n & 63;
                // fragment-pair order: d even, d+1 at lane+1 (= idx+4)
                int i0 = (((r >> 3) * 2 + (d >> 4)) * 32 + (r & 7) * 4 + (d & 3)) * 4
                       + ((d >> 3) & 1) * 2 + ((d >> 2) & 1);
                g_K[bh + tile * 2048 + i0]     = __uint_as_float(f2tf32(v0));
                g_K[bh + tile * 2048 + i0 + 4] = __uint_as_float(f2tf32(v1));
            } else {
                int tile = n >> 6, r = n & 63;
                int rl = r & 7;
                int p  = (r & 56) | ((rl >> 1) | ((rl & 1) << 2));
                // fragment-pair order: d even, d+1 at lane+4 (= idx+16)
                int i0 = (((p >> 3) * 2 + (d >> 4)) * 32 + (d & 7) * 4 + (p & 3)) * 4
                       + ((d >> 3) & 1) * 2 + ((p >> 2) & 1);
                g_V[bh + tile * 2048 + i0]      = __uint_as_float(f2tf32(v0));
                g_V[bh + tile * 2048 + i0 + 16] = __uint_as_float(f2tf32(v1));
            }
        }
    }
}

// ---------------------------------------------------------------------------
// Attention (R14 pipeline, LDS.128 fragment-pair loads): 4 warps, 32 query
// rows per warp, fused per-nt (QK mma -> mask -> exp2 -> PV mma). THREE
// cp.async buffers, one __syncthreads per tile, issue-before-compute.
// K/V read as uint4 fragment pairs: one LDS.128 feeds two mma.
// grid: (N/128, B*H)  block: 128
// smem: uint32[12288] = 48 KB. buf t%3: K at (t%3)*4096, V at +2048.
// ---------------------------------------------------------------------------
#define BM 128
#define BN 64

__global__ __launch_bounds__(128, 4) void attn_kernel(float* __restrict__ out)
{
    __shared__ uint32_t sm[12288];

    const int tid  = threadIdx.x;
    const int warp = tid >> 5;
    const int lane = tid & 31;
    const int grp  = lane >> 2;    // 0..7
    const int tig  = lane & 3;     // 0..3
    const int bh   = blockIdx.y;
    const int b    = bh >> 3;
    const int h    = bh & 7;
    const int n0   = blockIdx.x * BM;

    const float* __restrict__ Qg = g_Q + (size_t)bh * N_ * HS_;
    const float* __restrict__ Kg = g_K + (size_t)bh * N_ * HS_;   // frag-pair order
    const float* __restrict__ Vg = g_V + (size_t)bh * N_ * HS_;   // frag-pair order
    const unsigned* __restrict__ abase = g_adjbits + (size_t)b * N_ * NW_;

    const float qscale = 0.2550323215637855f;   // log2(e)/sqrt(HS)

    // ---- stage Q (scaled) into smem (stride 32) ----
    #pragma unroll
    for (int t = 0; t < 8; t++) {
        int f4 = tid + t * 128;           // 1024 float4
        int r  = f4 >> 3;
        int c  = (f4 & 7) << 2;
        float4 v = *(const float4*)(Qg + (size_t)(n0 + r) * HS_ + c);
        float* qs = (float*)sm + r * 32 + c;
        qs[0] = v.x * qscale; qs[1] = v.y * qscale;
        qs[2] = v.z * qscale; qs[3] = v.w * qscale;
    }
    __syncthreads();

    // warp owns rows [warp*32, warp*32+32): m-block 0 rows prow0, prow0+8;
    // m-block 1 rows prow0+16, prow0+24.
    const int prow0 = warp * 32 + grp;

    uint32_t qh0[4][4], qh1[4][4];
    #pragma unroll
    for (int kc = 0; kc < 4; kc++) {
        #pragma unroll
        for (int i = 0; i < 4; i++) {
            int col = kc*8 + tig + ((i >> 1) << 2);
            int roff = (i & 1) ? 8 : 0;
            qh0[kc][i] = f2tf32(((float*)sm)[(prow0 + roff)      * 32 + col]);
            qh1[kc][i] = f2tf32(((float*)sm)[(prow0 + 16 + roff) * 32 + col]);
        }
    }
    __syncthreads();   // smem becomes the K/V triple buffer

    const uint32_t smbase = (uint32_t)__cvta_generic_to_shared(sm);

    // async-copy one 64-row tile (K 2048 + V 2048 words) into buffer t%3
    auto issue_tile = [&](int t) {
        const float* ks = Kg + t * 2048 + tid * 16;
        const float* vs = Vg + t * 2048 + tid * 16;
        uint32_t kd = smbase + (t % 3) * 16384 + tid * 64;
        CP_ASYNC16(kd,        ks);
        CP_ASYNC16(kd + 16,   ks + 4);
        CP_ASYNC16(kd + 32,   ks + 8);
        CP_ASYNC16(kd + 48,   ks + 12);
        CP_ASYNC16(kd + 8192, vs);
        CP_ASYNC16(kd + 8208, vs + 4);
        CP_ASYNC16(kd + 8224, vs + 8);
        CP_ASYNC16(kd + 8240, vs + 12);
        CP_COMMIT();
    };

    issue_tile(0);
    issue_tile(1);

    float l0a = 0.0f, l1a = 0.0f, l0b = 0.0f, l1b = 0.0f;
    float o0[4][4] = {};   // m-block 0 output, C-fragment layout
    float o1[4][4] = {};   // m-block 1

    const unsigned FULL = 0xffffffffu;

    for (int it = 0; it < N_ / BN; it++) {
        const int kv0 = it * BN;
        const uint4* KF4 = (const uint4*)(sm + (it % 3) * 4096);
        const uint4* VF4 = KF4 + 512;

        // adjacency words for this warp's 4 rows (2 words each)
        const unsigned* ar = abase + (size_t)(n0 + prow0) * NW_ + (kv0 >> 5);
        unsigned awa0 = ar[0],            awa1 = ar[1];               // row prow0
        unsigned awb0 = ar[8*NW_],        awb1 = ar[8*NW_ + 1];       // +8
        unsigned awc0 = ar[16*NW_],       awc1 = ar[16*NW_ + 1];      // +16
        unsigned awd0 = ar[24*NW_],       awd1 = ar[24*NW_ + 1];      // +24

        CP_WAIT(1);          // tile `it` landed (tile it+1 may still be in flight)
        __syncthreads();     // also: every warp finished tile it-1 -> its buffer free

        if (it + 2 < N_ / BN)
            issue_tile(it + 2);   // refill buffer (it+2)%3, freed in iteration it-1

        // --- fused per-nt: QK (1-mma) -> mask -> exp2 -> PV ---
        #pragma unroll
        for (int nt = 0; nt < 8; nt++) {
            float s0[4] = {}, s1[4] = {};
            #pragma unroll
            for (int kcp = 0; kcp < 2; kcp++) {
                uint4 k = KF4[(nt*2 + kcp)*32 + lane];
                mma_tf32(s0, qh0[kcp*2],     k.x, k.y);
                mma_tf32(s0, qh0[kcp*2 + 1], k.z, k.w);
                mma_tf32(s1, qh1[kcp*2],     k.x, k.y);
                mma_tf32(s1, qh1[kcp*2 + 1], k.z, k.w);
            }

            int c0 = nt*8 + tig*2;        // even; c0,c0+1 share a word
            int sh = c0 & 31;
            unsigned wa = (c0 & 32) ? awa1 : awa0;
            unsigned wb = (c0 & 32) ? awb1 : awb0;
            unsigned wc = (c0 & 32) ? awc1 : awc0;
            unsigned wd = (c0 & 32) ? awd1 : awd0;

            s0[0] = ex2(((wa >> sh)     & 1) ? s0[0] : -1e30f);
            s0[1] = ex2(((wa >> (sh+1)) & 1) ? s0[1] : -1e30f);
            s0[2] = ex2(((wb >> sh)     & 1) ? s0[2] : -1e30f);
            s0[3] = ex2(((wb >> (sh+1)) & 1) ? s0[3] : -1e30f);
            s1[0] = ex2(((wc >> sh)     & 1) ? s1[0] : -1e30f);
            s1[1] = ex2(((wc >> (sh+1)) & 1) ? s1[1] : -1e30f);
            s1[2] = ex2(((wd >> sh)     & 1) ? s1[2] : -1e30f);
            s1[3] = ex2(((wd >> (sh+1)) & 1) ? s1[3] : -1e30f);

            uint32_t a0[4], a1[4];
            a0[0] = f2tf32(s0[0]); a0[1] = f2tf32(s0[2]);
            a0[2] = f2tf32(s0[1]); a0[3] = f2tf32(s0[3]);
            a1[0] = f2tf32(s1[0]); a1[1] = f2tf32(s1[2]);
            a1[2] = f2tf32(s1[1]); a1[3] = f2tf32(s1[3]);
            l0a += __uint_as_float(a0[0]) + __uint_as_float(a0[2]);
            l1a += __uint_as_float(a0[1]) + __uint_as_float(a0[3]);
            l0b += __uint_as_float(a1[0]) + __uint_as_float(a1[2]);
            l1b += __uint_as_float(a1[1]) + __uint_as_float(a1[3]);

            #pragma unroll
            for (int nt4p = 0; nt4p < 2; nt4p++) {
                uint4 v = VF4[(nt*2 + nt4p)*32 + lane];
                mma_tf32(o0[nt4p*2],     a0, v.x, v.y);
                mma_tf32(o0[nt4p*2 + 1], a0, v.z, v.w);
                mma_tf32(o1[nt4p*2],     a1, v.x, v.y);
                mma_tf32(o1[nt4p*2 + 1], a1, v.z, v.w);
            }
        }
        // no trailing sync: next iteration's top sync covers buffer reuse
    }

    // --- single deferred l reduction across the 4 tig lanes ---
    l0a += __shfl_xor_sync(FULL, l0a, 1); l0a += __shfl_xor_sync(FULL, l0a, 2);
    l1a += __shfl_xor_sync(FULL, l1a, 1); l1a += __shfl_xor_sync(FULL, l1a, 2);
    l0b += __shfl_xor_sync(FULL, l0b, 1); l0b += __shfl_xor_sync(FULL, l0b, 2);
    l1b += __shfl_xor_sync(FULL, l1b, 1); l1b += __shfl_xor_sync(FULL, l1b, 2);

    // --- finalize ---
    float i0a = 1.0f / l0a, i1a = 1.0f / l1a;
    float i0b = 1.0f / l0b, i1b = 1.0f / l1b;
    #pragma unroll
    for (int nt4 = 0; nt4 < 4; nt4++) {
        int col = h * HS_ + nt4*8 + tig*2;
        *(float2*)(out + ((size_t)(b * N_ + n0 + prow0))      * E_ + col) =
            make_float2(o0[nt4][0] * i0a, o0[nt4][1] * i0a);
        *(float2*)(out + ((size_t)(b * N_ + n0 + prow0 + 8))  * E_ + col) =
            make_float2(o0[nt4][2] * i1a, o0[nt4][3] * i1a);
        *(float2*)(out + ((size_t)(b * N_ + n0 + prow0 + 16)) * E_ + col) =
            make_float2(o1[nt4][0] * i0b, o1[nt4][1] * i0b);
        *(float2*)(out + ((size_t)(b * N_ + n0 + prow0 + 24)) * E_ + col) =
            make_float2(o1[nt4][2] * i1b, o1[nt4][3] * i1b);
    }
}

// ---------------------------------------------------------------------------
extern "C" void kernel_launch(void* const* d_in, const int* in_sizes, int n_in,
                              void* d_out, int out_size)
{
    const float* X   = (const float*)d_in[0];
    const void*  adj = d_in[1];
    const float* Wq  = (const float*)d_in[2];
    const float* bq  = (const float*)d_in[3];
    const float* Wk  = (const float*)d_in[4];
    const float* bk  = (const float*)d_in[5];
    const float* Wv  = (const float*)d_in[6];
    const float* bv  = (const float*)d_in[7];
    float*       out = (float*)d_out;

    detect_adj_kernel<<<1, 256>>>((const unsigned*)adj);

    pack_adj_kernel<<<(B_ * N_ * NW_) / 256, 256>>>(adj);

    dim3 pg(B_ * N_ / 128, E_ / 64, 3);
    proj_kernel<<<pg, 256>>>(X, Wq, bq, Wk, bk, Wv, bv);

    dim3 ag(N_ / BM, BHTOT);
    attn_kernel<<<ag, 128>>>(out);
}

// round 17
// speedup vs baseline: 1.1662x; 1.0056x over previous
#include <cuda_runtime.h>
#include <stdint.h>

#define B_   2
#define N_   4096
#define E_   256
#define H_   8
#define HS_  32
#define BHTOT (B_*H_)
#define NW_  (N_/32)          // adj bitmask words per row

// Scratch:
//  g_Q : fp32 [B,H,N,HS]
//  g_K : tf32-rounded, FRAGMENT-PAIR order (uint4/lane) per (bh, 64-row tile)
//  g_V : tf32-rounded, fragment-pair order with PV row permutation baked in
__device__ float    g_Q[(size_t)BHTOT * N_ * HS_];
__device__ float    g_K[(size_t)BHTOT * N_ * HS_];
__device__ float    g_V[(size_t)BHTOT * N_ * HS_];
__device__ unsigned g_adjbits[(size_t)B_ * N_ * NW_];
__device__ int      g_adj_mode;   // 0=int32{0,1}, 1=float32{0,1.0f}, 2=uint8{0,1}

// ---------------------------------------------------------------------------
// helpers
// ---------------------------------------------------------------------------
__device__ __forceinline__ uint32_t f2tf32(float f) {
    uint32_t r;
    asm("cvt.rna.tf32.f32 %0, %1;" : "=r"(r) : "f"(f));
    return r;
}
__device__ __forceinline__ float ex2(float x) {
    float r;
    asm("ex2.approx.f32 %0, %1;" : "=f"(r) : "f"(x));
    return r;
}
__device__ __forceinline__ void mma_tf32(float c[4], const uint32_t a[4],
                                         uint32_t b0, uint32_t b1) {
    asm volatile(
        "mma.sync.aligned.m16n8k8.row.col.f32.tf32.tf32.f32 "
        "{%0,%1,%2,%3}, {%4,%5,%6,%7}, {%8,%9}, {%0,%1,%2,%3};\n"
        : "+f"(c[0]), "+f"(c[1]), "+f"(c[2]), "+f"(c[3])
        : "r"(a[0]), "r"(a[1]), "r"(a[2]), "r"(a[3]), "r"(b0), "r"(b1));
}
#define CP_ASYNC16(dst_u32, src_ptr) \
    asm volatile("cp.async.ca.shared.global [%0], [%1], 16;\n" \
                 :: "r"(dst_u32), "l"(src_ptr))
#define CP_COMMIT() asm volatile("cp.async.commit_group;\n")
#define CP_WAIT(n)  asm volatile("cp.async.wait_group %0;\n" :: "n"(n))

// ---------------------------------------------------------------------------
// Detect adjacency storage dtype from bit patterns (deterministic, 64 KB scan).
// ---------------------------------------------------------------------------
__global__ __launch_bounds__(256) void detect_adj_kernel(const unsigned* __restrict__ a)
{
    __shared__ int s_ok[2];
    if (threadIdx.x == 0) { s_ok[0] = 1; s_ok[1] = 1; }
    __syncthreads();
    int ok_i = 1, ok_f = 1;
    for (int i = threadIdx.x; i < (1 << 14); i += 256) {
        unsigned w = a[i];
        if (w != 0u && w != 1u)          ok_i = 0;
        if (w != 0u && w != 0x3F800000u) ok_f = 0;
    }
    if (!ok_i) atomicAnd(&s_ok[0], 0);
    if (!ok_f) atomicAnd(&s_ok[1], 0);
    __syncthreads();
    if (threadIdx.x == 0) g_adj_mode = s_ok[0] ? 0 : (s_ok[1] ? 1 : 2);
}

// ---------------------------------------------------------------------------
// Pack adjacency to bitmask: g_adjbits[b*N + n][w] bit j = adj[b][n][w*32+j]
// ---------------------------------------------------------------------------
__global__ __launch_bounds__(256) void pack_adj_kernel(const void* __restrict__ adj_raw)
{
    int w = blockIdx.x * blockDim.x + threadIdx.x;   // word index
    unsigned bits = 0;
    if (g_adj_mode <= 1) {
        const int4* p = (const int4*)adj_raw + (size_t)w * 8;
        #pragma unroll
        for (int t = 0; t < 8; t++) {
            int4 v = p[t];
            bits |= (unsigned)(v.x != 0) << (t*4 + 0);
            bits |= (unsigned)(v.y != 0) << (t*4 + 1);
            bits |= (unsigned)(v.z != 0) << (t*4 + 2);
            bits |= (unsigned)(v.w != 0) << (t*4 + 3);
        }
    } else {
        const uint8_t* p = (const uint8_t*)adj_raw + (size_t)w * 32;
        #pragma unroll
        for (int j = 0; j < 32; j++)
            bits |= (unsigned)(p[j] != 0) << j;
    }
    g_adjbits[w] = bits;
}

// ---------------------------------------------------------------------------
// Projection via tf32 mma (2-mma compensated: X split hi/lo, W tf32-rounded).
// X chunks double-buffered via cp.async (issued one kb ahead, overlapping the
// mma phase). W (8 KB, L2-hot) staged synchronously, LDG hoisted before the
// first barrier. Scatter layouts unchanged (fragment-pair order for K/V).
// grid: (8192/128, 256/64, 3)  block: 256
// ---------------------------------------------------------------------------
__global__ __launch_bounds__(256, 2) void proj_kernel(
    const float* __restrict__ X,
    const float* __restrict__ Wq, const float* __restrict__ bq,
    const float* __restrict__ Wk, const float* __restrict__ bk,
    const float* __restrict__ Wv, const float* __restrict__ bv)
{
    const float* __restrict__ W;
    const float* __restrict__ bias;
    if (blockIdx.z == 0)      { W = Wq; bias = bq; }
    else if (blockIdx.z == 1) { W = Wk; bias = bk; }
    else                      { W = Wv; bias = bv; }

    __shared__ float    sX[2][128 * 36];   // fp32 X chunks, stride 36, double buffer
    __shared__ uint32_t sW[2048];          // tf32 W chunk, fragment order

    const int tid  = threadIdx.x;
    const int warp = tid >> 5;
    const int lane = tid & 31;
    const int grp  = lane >> 2;
    const int tig  = lane & 3;
    const int m0   = blockIdx.x * 128;
    const int e0   = blockIdx.y * 64;
    const int prow0 = warp * 16 + grp;
    const int prow1 = prow0 + 8;

    const uint32_t sxbase = (uint32_t)__cvta_generic_to_shared(&sX[0][0]);

    // issue one X chunk (128x32 fp32) into buffer kb&1 via cp.async
    auto issue_X = [&](int kb) {
        const int buf = kb & 1;
        #pragma unroll
        for (int t = 0; t < 4; t++) {
            int f4 = tid + t * 256;
            int r  = f4 >> 3;
            int c  = (f4 & 7) << 2;
            const float* src = X + (size_t)(m0 + r) * E_ + kb * 32 + c;
            uint32_t dst = sxbase + (uint32_t)(buf * (128*36) + r * 36 + c) * 4;
            CP_ASYNC16(dst, src);
        }
        CP_COMMIT();
    };

    issue_X(0);

    float acc[8][4] = {};

    for (int kb = 0; kb < 8; kb++) {
        const int k0 = kb * 32;
        const float* sXb = &sX[kb & 1][0];

        // W chunk LDGs hoisted (overlap previous mma tail / X wait)
        float4 wv0, wv1;
        int r0, c0, r1, c1;
        {
            int f4 = tid;
            r0 = f4 >> 3; c0 = (f4 & 7) << 2;
            wv0 = *(const float4*)(W + (size_t)(e0 + r0) * E_ + k0 + c0);
            f4 = tid + 256;
            r1 = f4 >> 3; c1 = (f4 & 7) << 2;
            wv1 = *(const float4*)(W + (size_t)(e0 + r1) * E_ + k0 + c1);
        }

        __syncthreads();   // everyone finished mma(kb-1): sW free, X buf kb&1 not in use
        {
            int base = ((r0 >> 3) * 4 + (c0 >> 3)) * 32 + (r0 & 7) * 4;
            int hf   = (c0 >> 2) & 1;
            sW[(base + 0) * 2 + hf] = f2tf32(wv0.x);
            sW[(base + 1) * 2 + hf] = f2tf32(wv0.y);
            sW[(base + 2) * 2 + hf] = f2tf32(wv0.z);
            sW[(base + 3) * 2 + hf] = f2tf32(wv0.w);
            base = ((r1 >> 3) * 4 + (c1 >> 3)) * 32 + (r1 & 7) * 4;
            hf   = (c1 >> 2) & 1;
            sW[(base + 0) * 2 + hf] = f2tf32(wv1.x);
            sW[(base + 1) * 2 + hf] = f2tf32(wv1.y);
            sW[(base + 2) * 2 + hf] = f2tf32(wv1.z);
            sW[(base + 3) * 2 + hf] = f2tf32(wv1.w);
        }
        CP_WAIT(0);        // X(kb) landed
        __syncthreads();   // sW + sX[kb&1] visible to all

        if (kb + 1 < 8)
            issue_X(kb + 1);   // fills the other buffer; overlaps the mma below

        #pragma unroll
        for (int kc = 0; kc < 4; kc++) {
            uint32_t xh[4], xl[4];
            #pragma unroll
            for (int i = 0; i < 4; i++) {
                int row = (i & 1) ? prow1 : prow0;
                int col = kc*8 + tig + ((i >> 1) << 2);
                float x = sXb[row * 36 + col];
                xh[i] = f2tf32(x);
                xl[i] = f2tf32(x - __uint_as_float(xh[i]));
            }
            #pragma unroll
            for (int nt = 0; nt < 8; nt++) {
                uint2 w = ((const uint2*)sW)[(nt*4 + kc)*32 + lane];
                mma_tf32(acc[nt], xh, w.x, w.y);
                mma_tf32(acc[nt], xl, w.x, w.y);
            }
        }
    }

    #pragma unroll
    for (int nt = 0; nt < 8; nt++) {
        int e = e0 + nt*8 + tig*2;           // even
        float2 bb = *(const float2*)(bias + e);
        int hh = e >> 5;
        int d  = e & 31;
        #pragma unroll
        for (int half = 0; half < 2; half++) {
            int m = m0 + (half ? prow1 : prow0);
            int b = m >> 12;
            int n = m & (N_ - 1);
            size_t bh = (size_t)(b*H_ + hh) * N_ * HS_;
            float v0 = acc[nt][half*2 + 0] + bb.x;
            float v1 = acc[nt][half*2 + 1] + bb.y;
            if (blockIdx.z == 0) {
                *(float2*)(g_Q + bh + (size_t)n * HS_ + d) = make_float2(v0, v1);
            } else if (blockIdx.z == 1) {
                int tile = n >> 6, r = n & 63;
                // fragment-pair order: d even, d+1 at lane+1 (= idx+4)
                int i0 = (((r >> 3) * 2 + (d >> 4)) * 32 + (r & 7) * 4 + (d & 3)) * 4
                       + ((d >> 3) & 1) * 2 + ((d >> 2) & 1);
                g_K[bh + tile * 2048 + i0]     = __uint_as_float(f2tf32(v0));
                g_K[bh + tile * 2048 + i0 + 4] = __uint_as_float(f2tf32(v1));
            } else {
                int tile = n >> 6, r = n & 63;
                int rl = r & 7;
                int p  = (r & 56) | ((rl >> 1) | ((rl & 1) << 2));
                // fragment-pair order: d even, d+1 at lane+4 (= idx+16)
                int i0 = (((p >> 3) * 2 + (d >> 4)) * 32 + (d & 7) * 4 + (p & 3)) * 4
                       + ((d >> 3) & 1) * 2 + ((p >> 2) & 1);
                g_V[bh + tile * 2048 + i0]      = __uint_as_float(f2tf32(v0));
                g_V[bh + tile * 2048 + i0 + 16] = __uint_as_float(f2tf32(v1));
            }
        }
    }
}

// ---------------------------------------------------------------------------
// Attention (R15 + uint2 adjacency loads): 4 warps, 32 query rows per warp,
// fused per-nt (QK mma -> mask -> exp2 -> PV mma). THREE cp.async buffers,
// one __syncthreads per tile, issue-before-compute. K/V read as uint4
// fragment pairs: one LDS.128 feeds two mma.
// grid: (N/128, B*H)  block: 128
// smem: uint32[12288] = 48 KB. buf t%3: K at (t%3)*4096, V at +2048.
// ---------------------------------------------------------------------------
#define BM 128
#define BN 64

__global__ __launch_bounds__(128, 4) void attn_kernel(float* __restrict__ out)
{
    __shared__ uint32_t sm[12288];

    const int tid  = threadIdx.x;
    const int warp = tid >> 5;
    const int lane = tid & 31;
    const int grp  = lane >> 2;    // 0..7
    const int tig  = lane & 3;     // 0..3
    const int bh   = blockIdx.y;
    const int b    = bh >> 3;
    const int h    = bh & 7;
    const int n0   = blockIdx.x * BM;

    const float* __restrict__ Qg = g_Q + (size_t)bh * N_ * HS_;
    const float* __restrict__ Kg = g_K + (size_t)bh * N_ * HS_;   // frag-pair order
    const float* __restrict__ Vg = g_V + (size_t)bh * N_ * HS_;   // frag-pair order
    const unsigned* __restrict__ abase = g_adjbits + (size_t)b * N_ * NW_;

    const float qscale = 0.2550323215637855f;   // log2(e)/sqrt(HS)

    // ---- stage Q (scaled) into smem (stride 32) ----
    #pragma unroll
    for (int t = 0; t < 8; t++) {
        int f4 = tid + t * 128;           // 1024 float4
        int r  = f4 >> 3;
        int c  = (f4 & 7) << 2;
        float4 v = *(const float4*)(Qg + (size_t)(n0 + r) * HS_ + c);
        float* qs = (float*)sm + r * 32 + c;
        qs[0] = v.x * qscale; qs[1] = v.y * qscale;
        qs[2] = v.z * qscale; qs[3] = v.w * qscale;
    }
    __syncthreads();

    // warp owns rows [warp*32, warp*32+32): m-block 0 rows prow0, prow0+8;
    // m-block 1 rows prow0+16, prow0+24.
    const int prow0 = warp * 32 + grp;

    uint32_t qh0[4][4], qh1[4][4];
    #pragma unroll
    for (int kc = 0; kc < 4; kc++) {
        #pragma unroll
        for (int i = 0; i < 4; i++) {
            int col = kc*8 + tig + ((i >> 1) << 2);
            int roff = (i & 1) ? 8 : 0;
            qh0[kc][i] = f2tf32(((float*)sm)[(prow0 + roff)      * 32 + col]);
            qh1[kc][i] = f2tf32(((float*)sm)[(prow0 + 16 + roff) * 32 + col]);
        }
    }
    __syncthreads();   // smem becomes the K/V triple buffer

    const uint32_t smbase = (uint32_t)__cvta_generic_to_shared(sm);

    // async-copy one 64-row tile (K 2048 + V 2048 words) into buffer t%3
    auto issue_tile = [&](int t) {
        const float* ks = Kg + t * 2048 + tid * 16;
        const float* vs = Vg + t * 2048 + tid * 16;
        uint32_t kd = smbase + (t % 3) * 16384 + tid * 64;
        CP_ASYNC16(kd,        ks);
        CP_ASYNC16(kd + 16,   ks + 4);
        CP_ASYNC16(kd + 32,   ks + 8);
        CP_ASYNC16(kd + 48,   ks + 12);
        CP_ASYNC16(kd + 8192, vs);
        CP_ASYNC16(kd + 8208, vs + 4);
        CP_ASYNC16(kd + 8224, vs + 8);
        CP_ASYNC16(kd + 8240, vs + 12);
        CP_COMMIT();
    };

    issue_tile(0);
    issue_tile(1);

    float l0a = 0.0f, l1a = 0.0f, l0b = 0.0f, l1b = 0.0f;
    float o0[4][4] = {};   // m-block 0 output, C-fragment layout
    float o1[4][4] = {};   // m-block 1

    const unsigned FULL = 0xffffffffu;

    // adjacency row pointers (uint2: two words per row per tile)
    const uint2* adjr = (const uint2*)(abase + (size_t)(n0 + prow0) * NW_);

    for (int it = 0; it < N_ / BN; it++) {
        const int w0 = it;                   // uint2 index: ((it*BN)>>5) / 2 = it
        const uint4* KF4 = (const uint4*)(sm + (it % 3) * 4096);
        const uint4* VF4 = KF4 + 512;

        // adjacency words for this warp's 4 rows (one LDG.64 each)
        uint2 Aa = adjr[w0];
        uint2 Ab = adjr[w0 + 4*NW_];         // +8 rows  (8 rows * NW_/2 uint2)
        uint2 Ac = adjr[w0 + 8*NW_];         // +16 rows
        uint2 Ad = adjr[w0 + 12*NW_];        // +24 rows
        unsigned awa0 = Aa.x, awa1 = Aa.y;
        unsigned awb0 = Ab.x, awb1 = Ab.y;
        unsigned awc0 = Ac.x, awc1 = Ac.y;
        unsigned awd0 = Ad.x, awd1 = Ad.y;

        CP_WAIT(1);          // tile `it` landed (tile it+1 may still be in flight)
        __syncthreads();     // also: every warp finished tile it-1 -> its buffer free

        if (it + 2 < N_ / BN)
            issue_tile(it + 2);   // refill buffer (it+2)%3, freed in iteration it-1

        // --- fused per-nt: QK (1-mma) -> mask -> exp2 -> PV ---
        #pragma unroll
        for (int nt = 0; nt < 8; nt++) {
            float s0[4] = {}, s1[4] = {};
            #pragma unroll
            for (int kcp = 0; kcp < 2; kcp++) {
                uint4 k = KF4[(nt*2 + kcp)*32 + lane];
                mma_tf32(s0, qh0[kcp*2],     k.x, k.y);
                mma_tf32(s0, qh0[kcp*2 + 1], k.z, k.w);
                mma_tf32(s1, qh1[kcp*2],     k.x, k.y);
                mma_tf32(s1, qh1[kcp*2 + 1], k.z, k.w);
            }

            int c0 = nt*8 + tig*2;        // even; c0,c0+1 share a word
            int sh = c0 & 31;
            unsigned wa = (c0 & 32) ? awa1 : awa0;
            unsigned wb = (c0 & 32) ? awb1 : awb0;
            unsigned wc = (c0 & 32) ? awc1 : awc0;
            unsigned wd = (c0 & 32) ? awd1 : awd0;

            s0[0] = ex2(((wa >> sh)     & 1) ? s0[0] : -1e30f);
            s0[1] = ex2(((wa >> (sh+1)) & 1) ? s0[1] : -1e30f);
            s0[2] = ex2(((wb >> sh)     & 1) ? s0[2] : -1e30f);
            s0[3] = ex2(((wb >> (sh+1)) & 1) ? s0[3] : -1e30f);
            s1[0] = ex2(((wc >> sh)     & 1) ? s1[0] : -1e30f);
            s1[1] = ex2(((wc >> (sh+1)) & 1) ? s1[1] : -1e30f);
            s1[2] = ex2(((wd >> sh)     & 1) ? s1[2] : -1e30f);
            s1[3] = ex2(((wd >> (sh+1)) & 1) ? s1[3] : -1e30f);

            uint32_t a0[4], a1[4];
            a0[0] = f2tf32(s0[0]); a0[1] = f2tf32(s0[2]);
            a0[2] = f2tf32(s0[1]); a0[3] = f2tf32(s0[3]);
            a1[0] = f2tf32(s1[0]); a1[1] = f2tf32(s1[2]);
            a1[2] = f2tf32(s1[1]); a1[3] = f2tf32(s1[3]);
            l0a += __uint_as_float(a0[0]) + __uint_as_float(a0[2]);
            l1a += __uint_as_float(a0[1]) + __uint_as_float(a0[3]);
            l0b += __uint_as_float(a1[0]) + __uint_as_float(a1[2]);
            l1b += __uint_as_float(a1[1]) + __uint_as_float(a1[3]);

            #pragma unroll
            for (int nt4p = 0; nt4p < 2; nt4p++) {
                uint4 v = VF4[(nt*2 + nt4p)*32 + lane];
                mma_tf32(o0[nt4p*2],     a0, v.x, v.y);
                mma_tf32(o0[nt4p*2 + 1], a0, v.z, v.w);
                mma_tf32(o1[nt4p*2],     a1, v.x, v.y);
                mma_tf32(o1[nt4p*2 + 1], a1, v.z, v.w);
            }
        }
        // no trailing sync: next iteration's top sync covers buffer reuse
    }

    // --- single deferred l reduction across the 4 tig lanes ---
    l0a += __shfl_xor_sync(FULL, l0a, 1); l0a += __shfl_xor_sync(FULL, l0a, 2);
    l1a += __shfl_xor_sync(FULL, l1a, 1); l1a += __shfl_xor_sync(FULL, l1a, 2);
    l0b += __shfl_xor_sync(FULL, l0b, 1); l0b += __shfl_xor_sync(FULL, l0b, 2);
    l1b += __shfl_xor_sync(FULL, l1b, 1); l1b += __shfl_xor_sync(FULL, l1b, 2);

    // --- finalize ---
    float i0a = 1.0f / l0a, i1a = 1.0f / l1a;
    float i0b = 1.0f / l0b, i1b = 1.0f / l1b;
    #pragma unroll
    for (int nt4 = 0; nt4 < 4; nt4++) {
        int col = h * HS_ + nt4*8 + tig*2;
        *(float2*)(out + ((size_t)(b * N_ + n0 + prow0))      * E_ + col) =
            make_float2(o0[nt4][0] * i0a, o0[nt4][1] * i0a);
        *(float2*)(out + ((size_t)(b * N_ + n0 + prow0 + 8))  * E_ + col) =
            make_float2(o0[nt4][2] * i1a, o0[nt4][3] * i1a);
        *(float2*)(out + ((size_t)(b * N_ + n0 + prow0 + 16)) * E_ + col) =
            make_float2(o1[nt4][0] * i0b, o1[nt4][1] * i0b);
        *(float2*)(out + ((size_t)(b * N_ + n0 + prow0 + 24)) * E_ + col) =
            make_float2(o1[nt4][2] * i1b, o1[nt4][3] * i1b);
    }
}

// ---------------------------------------------------------------------------
extern "C" void kernel_launch(void* const* d_in, const int* in_sizes, int n_in,
                              void* d_out, int out_size)
{
    const float* X   = (const float*)d_in[0];
    const void*  adj = d_in[1];
    const float* Wq  = (const float*)d_in[2];
    const float* bq  = (const float*)d_in[3];
    const float* Wk  = (const float*)d_in[4];
    const float* bk  = (const float*)d_in[5];
    const float* Wv  = (const float*)d_in[6];
    const float* bv  = (const float*)d_in[7];
    float*       out = (float*)d_out;

    detect_adj_kernel<<<1, 256>>>((const unsigned*)adj);

    pack_adj_kernel<<<(B_ * N_ * NW_) / 256, 256>>>(adj);

    dim3 pg(B_ * N_ / 128, E_ / 64, 3);
    proj_kernel<<<pg, 256>>>(X, Wq, bq, Wk, bk, Wv, bv);

    dim3 ag(N_ / BM, BHTOT);
    attn_kernel<<<ag, 128>>>(out);
}